// round 14
// baseline (speedup 1.0000x reference)
#include <cuda_runtime.h>
#include <cstdint>

#define SEQ 2048
#define NB 64
#define NF 16
#define HD 512
#define ROWB 2048                        // bytes per hidden row (gmem)
#define ROWP 2064                        // staged row stride (129 units ≡1 mod 8)
#define SLOT_PAD 516                     // floats per f-row: conflict-free
#define SLOT_BYTES (NF * SLOT_PAD * 4)   // 33024
#define STAGE_TOK 8
#define STAGE_B (STAGE_TOK * ROWP)       // 16512
#define RING 3
#define CNT_OFF (SLOT_BYTES + RING * STAGE_B)     // 82560
#define SMEM_TOTAL (CNT_OFF + NB * 4)             // 82816 -> 2 blocks/SM
#define MAX_G 256                        // 8-token groups per batch
#define MAX_ITEMS (MAX_G * NB)           // item = g*64 + b
#define GRID_X 296                       // 2 blocks/SM

// Scratch (allocation-free rule: __device__ globals)
__device__ int g_list[NB * SEQ];   // packed: token_pos | (seg << 16), compacted per batch
__device__ int g_cnt[NB];

__device__ __forceinline__ unsigned long long ffma2(unsigned long long a,
                                                    unsigned long long b,
                                                    unsigned long long c) {
    unsigned long long d;
    asm("fma.rn.f32x2 %0, %1, %2, %3;" : "=l"(d) : "l"(a), "l"(b), "l"(c));
    return d;
}

__device__ __forceinline__ void cp16(void* dst_smem, const void* src) {
    unsigned saddr = (unsigned)__cvta_generic_to_shared(dst_smem);
    asm volatile("cp.async.cg.shared.global [%0], [%1], 16;" :: "r"(saddr), "l"(src));
}
__device__ __forceinline__ void cp_commit() {
    asm volatile("cp.async.commit_group;");
}
template <int N>
__device__ __forceinline__ void cp_wait() {
    asm volatile("cp.async.wait_group %0;" :: "n"(N));
}
__device__ __forceinline__ void bar_sync(int id) {
    asm volatile("bar.sync %0, 256;" :: "r"(id) : "memory");
}
__device__ __forceinline__ void bar_arrive(int id) {
    asm volatile("bar.arrive %0, 256;" :: "r"(id) : "memory");
}

// ---------------------------------------------------------------------------
// Block-wide exclusive scan over 256 threads
// ---------------------------------------------------------------------------
__device__ __forceinline__ int block_exscan(int v, int* sh) {
    int lane = threadIdx.x & 31;
    int w = threadIdx.x >> 5;
    int incl = v;
#pragma unroll
    for (int o = 1; o < 32; o <<= 1) {
        int n = __shfl_up_sync(0xFFFFFFFFu, incl, o);
        if (lane >= o) incl += n;
    }
    if (lane == 31) sh[w] = incl;
    __syncthreads();
    if (threadIdx.x < 8) {
        int x = sh[threadIdx.x];
#pragma unroll
        for (int o = 1; o < 8; o <<= 1) {
            int n = __shfl_up_sync(0xFFu, x, o);
            if (threadIdx.x >= (unsigned)o) x += n;
        }
        sh[threadIdx.x] = x;
    }
    __syncthreads();
    int wofs = (w == 0) ? 0 : sh[w - 1];
    return wofs + incl - v;
}

// ---------------------------------------------------------------------------
// Kernel 1 (fused): zero output (all 256 blocks) + per-batch span ids +
// compaction (first 64 blocks).
// ---------------------------------------------------------------------------
__global__ __launch_bounds__(256) void seg_zero_kernel(const int* __restrict__ labels,
                                                       const int* pB, const int* pI,
                                                       const int* pMS,
                                                       float* __restrict__ out,
                                                       int out_n) {
    {
        int tid = blockIdx.x * 256 + threadIdx.x;
        int nthreads = gridDim.x * 256;
        int n4 = out_n >> 2;
        float4 z = make_float4(0.f, 0.f, 0.f, 0.f);
        for (int i = tid; i < n4; i += nthreads)
            reinterpret_cast<float4*>(out)[i] = z;
        for (int i = (n4 << 2) + tid; i < out_n; i += nthreads)
            out[i] = 0.0f;
    }
    if (blockIdx.x >= NB) return;

    __shared__ int sh[8];
    int b = blockIdx.x;
    int t = threadIdx.x;
    int Bv = pB ? *pB : 1;
    int Iv = pI ? *pI : 2;
    int MS = pMS ? *pMS : 512;

    const int4* row = reinterpret_cast<const int4*>(labels + b * SEQ) + t * 2;
    int4 a = row[0];
    int4 c = row[1];
    int lab[8] = {a.x, a.y, a.z, a.w, c.x, c.y, c.z, c.w};

    int incl[8];
    int csum = 0;
#pragma unroll
    for (int i = 0; i < 8; i++) {
        csum += (lab[i] == Bv);
        incl[i] = csum;
    }
    int ex = block_exscan(csum, sh);

    int seg[8], vfl[8];
    int vtot = 0;
#pragma unroll
    for (int i = 0; i < 8; i++) {
        seg[i] = ex + incl[i] - 1;
        vfl[i] = ((lab[i] == Bv) || (lab[i] == Iv)) && seg[i] >= 0 && seg[i] < MS;
        vtot += vfl[i];
    }
    __syncthreads();
    int vex = block_exscan(vtot, sh);

    int pos = vex;
#pragma unroll
    for (int i = 0; i < 8; i++) {
        if (vfl[i]) {
            g_list[b * SEQ + pos] = (t * 8 + i) | (seg[i] << 16);
            pos++;
        }
    }
    if (t == 255) g_cnt[b] = vex + vtot;
}

// ---------------------------------------------------------------------------
// Kernel 2: warp-specialized gather-projection with WHOLE-ROW DRAM bursts.
//
// Item = stage = 8 compacted tokens x FULL 512 d of batch b (item = g*64+b).
// Each staged row is loaded by ONE producer warp as 4 back-to-back cp16
// covering the contiguous 2KB -> the memory controller sees one 2KB burst
// per row (1-2 DRAM activates) instead of 4-16 temporally-scattered
// fragments (the ~2.1 TB/s activate-rate cap of R4-R13).
//
// Block = 8 warps: consumers w0-3 (one per SMSP), producers w4-7.
// Ring of 3 stages; named-barrier handshake per slot:
//   producer: [i>=3: sync free(i%3)] issue(i); commit;
//             [i>=1: wait_group<1>; arrive full((i-1)%3)]  -> 2 stages in flight
//   consumer: sync full(i%3); compute; scatter; arrive free(i%3)
//
// Consumer w=q owns d-quarter q: lane (tg = l>>3, fh = l&7) tiles tokens
// {tg, tg+4} x f = {fh, fh+8}; 32 chunks x (2 S + 2 H LDS.128 conflict-free
// + 8 FFMA2). Full-d partial per quarter -> atomicAdd.
// ---------------------------------------------------------------------------
__global__ __launch_bounds__(256, 2) void proj_kernel(const float* __restrict__ hidden,
                                                      const float* __restrict__ slot,
                                                      const int* pMS,
                                                      float* __restrict__ out) {
    extern __shared__ float smem[];
    float* slot_sh = smem;
    char* ring = reinterpret_cast<char*>(smem) + SLOT_BYTES;
    int* cnts = reinterpret_cast<int*>(reinterpret_cast<char*>(smem) + CNT_OFF);
    int MS = pMS ? *pMS : 512;

    // stage slot_embs transposed (vectorized): slot[d][f] -> slot_sh[f][d]
    for (int i = threadIdx.x; i < (HD * NF) / 4; i += 256) {
        int d = i >> 2;
        int f4 = (i & 3) * 4;
        float4 v = reinterpret_cast<const float4*>(slot)[i];
        slot_sh[(f4 + 0) * SLOT_PAD + d] = v.x;
        slot_sh[(f4 + 1) * SLOT_PAD + d] = v.y;
        slot_sh[(f4 + 2) * SLOT_PAD + d] = v.z;
        slot_sh[(f4 + 3) * SLOT_PAD + d] = v.w;
    }
    if (threadIdx.x < NB) cnts[threadIdx.x] = g_cnt[threadIdx.x];
    __syncthreads();

    int w = threadIdx.x >> 5;
    int lane = threadIdx.x & 31;

    // count valid items for this block (uniform)
    int T = 0;
    for (int it = blockIdx.x; it < MAX_ITEMS; it += GRID_X)
        if ((it >> 6) * STAGE_TOK < cnts[it & 63]) T++;
    if (T == 0) return;

    auto next_valid = [&](int it) {
        while (it < MAX_ITEMS && (it >> 6) * STAGE_TOK >= cnts[it & 63]) it += GRID_X;
        return it;
    };

    if (w >= 4) {
        // ------------------------- PRODUCER (w4..w7) -------------------------
        int p = w - 4;
        const char* hbytes = reinterpret_cast<const char*>(hidden);
        int it = next_valid(blockIdx.x);

        for (int i = 0; i < T; i++) {
            if (i >= RING) bar_sync(4 + i % RING);

            // compute the two row offsets for tokens {p, p+4} of this item
            int g = it >> 6;
            int b = it & 63;
            int cnt = cnts[b];
            int t0 = g * STAGE_TOK;
            char* buf = ring + (i % RING) * STAGE_B;
#pragma unroll
            for (int m = 0; m < 2; m++) {
                int tok = p + 4 * m;
                int ti = t0 + tok;
                if (ti >= cnt) ti = cnt - 1;
                unsigned rofs = ((unsigned)b * SEQ +
                                 (unsigned)(g_list[b * SEQ + ti] & 0xFFFF)) * ROWB;
                const char* src = hbytes + rofs + lane * 16;
                char* dst = buf + tok * ROWP + lane * 16;
                // whole 2KB row as 4 contiguous 512B cp16 bursts
#pragma unroll
                for (int k = 0; k < 4; k++)
                    cp16(dst + k * 512, src + k * 512);
            }
            cp_commit();

            if (i >= 1) {
                cp_wait<1>();                    // stage i-1 fully landed
                bar_arrive(1 + (i - 1) % RING);  // publish full(i-1)
            }
            it = next_valid(it + GRID_X);
        }
        cp_wait<0>();
        bar_arrive(1 + (T - 1) % RING);
    } else {
        // ------------------------- CONSUMER (w0..w3) -------------------------
        int q = w;                // d-quarter
        int tg = lane >> 3;       // token base (0..3); tokens {tg, tg+4}
        int fh = lane & 7;        // f half
        int it = next_valid(blockIdx.x);
        const float* sbase = slot_sh + fh * SLOT_PAD + q * 128;

        for (int i = 0; i < T; i++) {
            bar_sync(1 + i % RING);    // stage i ready

            const char* buf = ring + (i % RING) * STAGE_B + tg * ROWP + q * 512;
            unsigned long long a00 = 0, a01 = 0, a10 = 0, a11 = 0;
#pragma unroll 8
            for (int c = 0; c < 32; c++) {
                ulonglong2 S0 = *reinterpret_cast<const ulonglong2*>(sbase + c * 4);
                ulonglong2 S1 = *reinterpret_cast<const ulonglong2*>(sbase + 8 * SLOT_PAD + c * 4);
                ulonglong2 H0 = *reinterpret_cast<const ulonglong2*>(buf + c * 16);
                ulonglong2 H1 = *reinterpret_cast<const ulonglong2*>(buf + 4 * ROWP + c * 16);
                a00 = ffma2(H0.x, S0.x, a00);
                a00 = ffma2(H0.y, S0.y, a00);
                a01 = ffma2(H0.x, S1.x, a01);
                a01 = ffma2(H0.y, S1.y, a01);
                a10 = ffma2(H1.x, S0.x, a10);
                a10 = ffma2(H1.y, S0.y, a10);
                a11 = ffma2(H1.x, S1.x, a11);
                a11 = ffma2(H1.y, S1.y, a11);
            }

            // scatter quarter-d sums for this item's tokens {tg, tg+4}
            int g = it >> 6;
            int b = it & 63;
            int cnt = cnts[b];
            int t0 = g * STAGE_TOK;
            const int* lst = g_list + b * SEQ;
#pragma unroll
            for (int m = 0; m < 2; m++) {
                int ti = t0 + tg + 4 * m;
                if (ti < cnt) {
                    int pk = lst[ti];
                    float* op = out + ((size_t)b * MS + (pk >> 16)) * NF;
                    unsigned long long vx = m ? a10 : a00;
                    unsigned long long vy = m ? a11 : a01;
                    float2 v0 = *reinterpret_cast<float2*>(&vx);
                    float2 v1 = *reinterpret_cast<float2*>(&vy);
                    atomicAdd(op + fh, v0.x + v0.y);
                    atomicAdd(op + fh + 8, v1.x + v1.y);
                }
            }

            bar_arrive(4 + i % RING);  // slot free
            it = next_valid(it + GRID_X);
        }
    }
}

// ---------------------------------------------------------------------------
extern "C" void kernel_launch(void* const* d_in, const int* in_sizes, int n_in,
                              void* d_out, int out_size) {
    const float* hidden = (const float*)d_in[0];
    const float* slot = (const float*)d_in[1];
    const int* labels = (const int*)d_in[2];
    const int* pB = (n_in > 3) ? (const int*)d_in[3] : nullptr;
    const int* pI = (n_in > 4) ? (const int*)d_in[4] : nullptr;
    const int* pMS = (n_in > 5) ? (const int*)d_in[5] : nullptr;
    float* out = (float*)d_out;

    static bool attr_set = false;
    if (!attr_set) {
        cudaFuncSetAttribute(proj_kernel, cudaFuncAttributeMaxDynamicSharedMemorySize,
                             SMEM_TOTAL);
        attr_set = true;
    }

    seg_zero_kernel<<<256, 256>>>(labels, pB, pI, pMS, out, out_size);
    proj_kernel<<<GRID_X, 256, SMEM_TOTAL>>>(hidden, slot, pMS, out);
}

// round 15
// speedup vs baseline: 1.3465x; 1.3465x over previous
#include <cuda_runtime.h>
#include <cstdint>

#define SEQ 2048
#define NB 64
#define NF 16
#define HD 512
#define ROWB 2048                        // bytes per hidden row (gmem)
#define SLOT_PAD 516                     // floats per f-row: 129 units ≡1 mod 8, conflict-free
#define SLOT_BYTES (NF * SLOT_PAD * 4)   // 33024
#define U_TOK 32                         // tokens per unit (block)
#define W_TOK 16                         // tokens per warp
#define TROW 144                         // staged token-row stride (9 units ≡1 mod 8)
#define STAGE_B (W_TOK * TROW)           // 2304
#define RING_STAGES 4
#define NW 8                             // warps/block: 4 d-quarters x 2 token-halves
#define CNT_OFF (SLOT_BYTES + NW * RING_STAGES * STAGE_B)   // 106752
#define SMEM_TOTAL (CNT_OFF + NB * 4)                       // 107008 -> 2 blocks/SM
#define N_UNITS ((SEQ / U_TOK) * NB)     // 4096, u = x*64 + b
#define GRID_X 296                       // 2/SM

// Scratch (allocation-free rule: __device__ globals)
__device__ int g_list[NB * SEQ];   // packed: token_pos | (seg << 16), compacted per batch
__device__ int g_cnt[NB];

__device__ __forceinline__ unsigned long long ffma2(unsigned long long a,
                                                    unsigned long long b,
                                                    unsigned long long c) {
    unsigned long long d;
    asm("fma.rn.f32x2 %0, %1, %2, %3;" : "=l"(d) : "l"(a), "l"(b), "l"(c));
    return d;
}

__device__ __forceinline__ void cp16(void* dst_smem, const void* src) {
    unsigned saddr = (unsigned)__cvta_generic_to_shared(dst_smem);
    asm volatile("cp.async.cg.shared.global [%0], [%1], 16;" :: "r"(saddr), "l"(src));
}
__device__ __forceinline__ void cp_commit() {
    asm volatile("cp.async.commit_group;");
}
template <int N>
__device__ __forceinline__ void cp_wait() {
    asm volatile("cp.async.wait_group %0;" :: "n"(N));
}

// ---------------------------------------------------------------------------
// Block-wide exclusive scan over 256 threads
// ---------------------------------------------------------------------------
__device__ __forceinline__ int block_exscan(int v, int* sh) {
    int lane = threadIdx.x & 31;
    int w = threadIdx.x >> 5;
    int incl = v;
#pragma unroll
    for (int o = 1; o < 32; o <<= 1) {
        int n = __shfl_up_sync(0xFFFFFFFFu, incl, o);
        if (lane >= o) incl += n;
    }
    if (lane == 31) sh[w] = incl;
    __syncthreads();
    if (threadIdx.x < 8) {
        int x = sh[threadIdx.x];
#pragma unroll
        for (int o = 1; o < 8; o <<= 1) {
            int n = __shfl_up_sync(0xFFu, x, o);
            if (threadIdx.x >= (unsigned)o) x += n;
        }
        sh[threadIdx.x] = x;
    }
    __syncthreads();
    int wofs = (w == 0) ? 0 : sh[w - 1];
    return wofs + incl - v;
}

// ---------------------------------------------------------------------------
// Kernel 1 (fused): zero output (all 256 blocks) + per-batch span ids +
// compaction (first 64 blocks).
// ---------------------------------------------------------------------------
__global__ __launch_bounds__(256) void seg_zero_kernel(const int* __restrict__ labels,
                                                       const int* pB, const int* pI,
                                                       const int* pMS,
                                                       float* __restrict__ out,
                                                       int out_n) {
    {
        int tid = blockIdx.x * 256 + threadIdx.x;
        int nthreads = gridDim.x * 256;
        int n4 = out_n >> 2;
        float4 z = make_float4(0.f, 0.f, 0.f, 0.f);
        for (int i = tid; i < n4; i += nthreads)
            reinterpret_cast<float4*>(out)[i] = z;
        for (int i = (n4 << 2) + tid; i < out_n; i += nthreads)
            out[i] = 0.0f;
    }
    if (blockIdx.x >= NB) return;

    __shared__ int sh[8];
    int b = blockIdx.x;
    int t = threadIdx.x;
    int Bv = pB ? *pB : 1;
    int Iv = pI ? *pI : 2;
    int MS = pMS ? *pMS : 512;

    const int4* row = reinterpret_cast<const int4*>(labels + b * SEQ) + t * 2;
    int4 a = row[0];
    int4 c = row[1];
    int lab[8] = {a.x, a.y, a.z, a.w, c.x, c.y, c.z, c.w};

    int incl[8];
    int csum = 0;
#pragma unroll
    for (int i = 0; i < 8; i++) {
        csum += (lab[i] == Bv);
        incl[i] = csum;
    }
    int ex = block_exscan(csum, sh);

    int seg[8], vfl[8];
    int vtot = 0;
#pragma unroll
    for (int i = 0; i < 8; i++) {
        seg[i] = ex + incl[i] - 1;
        vfl[i] = ((lab[i] == Bv) || (lab[i] == Iv)) && seg[i] >= 0 && seg[i] < MS;
        vtot += vfl[i];
    }
    __syncthreads();
    int vex = block_exscan(vtot, sh);

    int pos = vex;
#pragma unroll
    for (int i = 0; i < 8; i++) {
        if (vfl[i]) {
            g_list[b * SEQ + pos] = (t * 8 + i) | (seg[i] << 16);
            pos++;
        }
    }
    if (t == 255) g_cnt[b] = vex + vtot;
}

// ---------------------------------------------------------------------------
// Kernel 2: warp-autonomous gather-projection (R8 structure) with
// 128B-CONTIGUOUS staging: each cp16 warp-instr covers 4 rows x 128B
// (4 lines = 4 L1tex wavefronts) instead of 8 rows x 64B (8 wf).
//
// Unit = 32 compacted tokens (u = x*64 + b). Warp (q = w&3, h = w>>2) owns
// d-quarter q of tokens [16h, 16h+16). Stage = 16 tok x 32 d, rows 144B.
//   staging: lane (r = l>>3, ch = l&7); instr m covers rows {4m+r}, bytes
//            ch*16 of the row's 128B stage segment (gmem-contiguous).
//            store banks: (4m + r + ch)&7 -> each bank exactly 4x (minimal).
//   reads:   H token t = tg + 4j, chunk c: bank = (t + c)&7, tg 0..3 ->
//            4 distinct banks; S rows stride 129 ≡ 1 -> conflict-free.
// Issue cursor runs 3 stages ahead through a 4-slot ring; stage stream is
// continuous across the warp's whole unit list.
// ---------------------------------------------------------------------------
__global__ __launch_bounds__(256, 2) void proj_kernel(const float* __restrict__ hidden,
                                                      const float* __restrict__ slot,
                                                      const int* pMS,
                                                      float* __restrict__ out) {
    extern __shared__ float smem[];
    float* slot_sh = smem;
    char* ringbase = reinterpret_cast<char*>(smem) + SLOT_BYTES;
    int* cnts = reinterpret_cast<int*>(reinterpret_cast<char*>(smem) + CNT_OFF);
    int MS = pMS ? *pMS : 512;

    // stage slot_embs transposed (vectorized): slot[d][f] -> slot_sh[f][d]
    for (int i = threadIdx.x; i < (HD * NF) / 4; i += 256) {
        int d = i >> 2;
        int f4 = (i & 3) * 4;
        float4 v = reinterpret_cast<const float4*>(slot)[i];
        slot_sh[(f4 + 0) * SLOT_PAD + d] = v.x;
        slot_sh[(f4 + 1) * SLOT_PAD + d] = v.y;
        slot_sh[(f4 + 2) * SLOT_PAD + d] = v.z;
        slot_sh[(f4 + 3) * SLOT_PAD + d] = v.w;
    }
    if (threadIdx.x < NB) cnts[threadIdx.x] = g_cnt[threadIdx.x];
    __syncthreads();

    int w = threadIdx.x >> 5;
    int lane = threadIdx.x & 31;
    int q = w & 3;            // d-quarter
    int h = w >> 2;           // token half
    int r = lane >> 3;        // staging row-in-quad (0..3) == compute token base tg
    int ch = lane & 7;        // staging chunk (0..7)     == compute f half fh
    char* ring0 = ringbase + w * RING_STAGES * STAGE_B;

    // staging dst offsets (unit-invariant): instr m -> row 4m+r, byte ch*16
    int dst[4];
#pragma unroll
    for (int m = 0; m < 4; m++)
        dst[m] = (4 * m + r) * TROW + ch * 16;

    const char* hbase = reinterpret_cast<const char*>(hidden) + q * 512;

    // total stages for this block (uniform across its warps)
    int total = 0;
    for (int u = blockIdx.x; u < N_UNITS; u += GRID_X)
        if ((u >> 6) * U_TOK < cnts[u & 63]) total++;
    if (total == 0) return;
    total *= 4;

    // ---- issue cursor ----
    int u_i = blockIdx.x;
    while ((u_i >> 6) * U_TOK >= cnts[u_i & 63]) u_i += GRID_X;
    unsigned ofs_i[4];        // row byte-offsets for tokens {r+4m}
    int s_i = 0;
    int isl = 0;

    auto load_ofs = [&](int u) {
        int x = u >> 6;
        int b = u & 63;
        int cnt = cnts[b];
        int t0 = x * U_TOK + h * W_TOK;
#pragma unroll
        for (int m = 0; m < 4; m++) {
            int ti = t0 + r + 4 * m;
            if (ti >= cnt) ti = cnt - 1;
            ofs_i[m] = ((unsigned)b * SEQ + (unsigned)(g_list[b * SEQ + ti] & 0xFFFF)) * ROWB;
        }
    };
    load_ofs(u_i);

    auto issue_one = [&]() {
        char* buf = ring0 + (isl & 3) * STAGE_B;
        unsigned sub = (unsigned)(s_i * 128 + ch * 16);
#pragma unroll
        for (int m = 0; m < 4; m++)
            cp16(buf + dst[m], hbase + ofs_i[m] + sub);
        cp_commit();
        isl++;
        if (++s_i == 4) {
            s_i = 0;
            do {
                u_i += GRID_X;
            } while (u_i < N_UNITS && (u_i >> 6) * U_TOK >= cnts[u_i & 63]);
            if (u_i < N_UNITS) load_ofs(u_i);
        }
    };

    int pre = total < 3 ? total : 3;
    for (int k = 0; k < pre; k++) issue_one();

    // ---- compute cursor ----
    int u_c = blockIdx.x;
    while ((u_c >> 6) * U_TOK >= cnts[u_c & 63]) u_c += GRID_X;

    unsigned long long acc[4][2];
    const float* sbase = slot_sh + ch * SLOT_PAD + q * 128;

    for (int i = 0; i < total; i++) {
        int ahead = total - 1 - i;
        if (ahead >= 2) cp_wait<2>();
        else if (ahead == 1) cp_wait<1>();
        else cp_wait<0>();
        __syncwarp();

        int s = i & 3;
        if (s == 0) {
#pragma unroll
            for (int j = 0; j < 4; j++) {
                acc[j][0] = 0ull;
                acc[j][1] = 0ull;
            }
        }

        // base pointers: all inner offsets are compile-time constants
        const char* hb = ring0 + (i & 3) * STAGE_B + r * TROW;   // token tg = r
        const float* s0p = sbase + s * 32;
        const float* s1p = s0p + 8 * SLOT_PAD;
#pragma unroll
        for (int c = 0; c < 8; c++) {
            ulonglong2 S0 = *reinterpret_cast<const ulonglong2*>(s0p + c * 4);
            ulonglong2 S1 = *reinterpret_cast<const ulonglong2*>(s1p + c * 4);
#pragma unroll
            for (int j = 0; j < 4; j++) {
                // token r + 4j, chunk c: offset = 4j*144 + 16c (const)
                ulonglong2 H = *reinterpret_cast<const ulonglong2*>(hb + j * (4 * TROW) + c * 16);
                acc[j][0] = ffma2(H.x, S0.x, acc[j][0]);
                acc[j][0] = ffma2(H.y, S0.y, acc[j][0]);
                acc[j][1] = ffma2(H.x, S1.x, acc[j][1]);
                acc[j][1] = ffma2(H.y, S1.y, acc[j][1]);
            }
        }

        if (s == 3) {
            int x = u_c >> 6;
            int b = u_c & 63;
            int cnt = cnts[b];
            int t0 = x * U_TOK + h * W_TOK;
            const int* lst = g_list + b * SEQ;
#pragma unroll
            for (int j = 0; j < 4; j++) {
                int ti = t0 + r + 4 * j;
                if (ti < cnt) {
                    int p = lst[ti];
                    float* op = out + ((size_t)b * MS + (p >> 16)) * NF;
                    float2 v0 = *reinterpret_cast<float2*>(&acc[j][0]);
                    float2 v1 = *reinterpret_cast<float2*>(&acc[j][1]);
                    atomicAdd(op + ch, v0.x + v0.y);
                    atomicAdd(op + ch + 8, v1.x + v1.y);
                }
            }
            do {
                u_c += GRID_X;
            } while (u_c < N_UNITS && (u_c >> 6) * U_TOK >= cnts[u_c & 63]);
        }

        __syncwarp();   // ring slot fully read before refill
        if (isl < total) issue_one();
    }
}

// ---------------------------------------------------------------------------
extern "C" void kernel_launch(void* const* d_in, const int* in_sizes, int n_in,
                              void* d_out, int out_size) {
    const float* hidden = (const float*)d_in[0];
    const float* slot = (const float*)d_in[1];
    const int* labels = (const int*)d_in[2];
    const int* pB = (n_in > 3) ? (const int*)d_in[3] : nullptr;
    const int* pI = (n_in > 4) ? (const int*)d_in[4] : nullptr;
    const int* pMS = (n_in > 5) ? (const int*)d_in[5] : nullptr;
    float* out = (float*)d_out;

    static bool attr_set = false;
    if (!attr_set) {
        cudaFuncSetAttribute(proj_kernel, cudaFuncAttributeMaxDynamicSharedMemorySize,
                             SMEM_TOTAL);
        attr_set = true;
    }

    seg_zero_kernel<<<256, 256>>>(labels, pB, pI, pMS, out, out_size);
    proj_kernel<<<GRID_X, 256, SMEM_TOTAL>>>(hidden, slot, pMS, out);
}